// round 2
// baseline (speedup 1.0000x reference)
#include <cuda_runtime.h>
#include <math.h>

#define B_    16
#define S_    8192
#define D_    128
#define H_    512
#define NROT  3
#define NMAT  (B_ * NROT)          // 48
#define MATSZ (D_ * D_)            // 16384
#define W2ROWS (NROT * D_ * D_)    // 49152

// ---------------- scratch (static device globals; no allocs) ----------------
__device__ float g_partial[B_ * 8 * D_];   // per-chunk partial sums for mean
__device__ float g_h[B_ * H_];             // gelu hidden
__device__ float g_P[W2ROWS * B_];         // P[r][b]  (r = i*D*D + d*D + e)
__device__ float g_Bm[NMAT * MATSZ];       // B = 0.5*(P - P^T) / 8   (m = b*3+i)
__device__ float g_T0[NMAT * MATSZ];
__device__ float g_T1[NMAT * MATSZ];
__device__ float g_Rt[B_ * MATSZ];         // rot0@rot1
__device__ float g_R [B_ * MATSZ];         // rot0@rot1@rot2

// Buffer IDs for passing __device__ globals "by reference" from host.
// (Passing the symbols directly as kernel args from host code passes the
//  HOST shadow address — on GB300 with ATS that silently reads/writes host
//  memory instead of faulting. Round-1 bug.)
#define BUF_BM 0
#define BUF_T0 1
#define BUF_T1 2
#define BUF_RT 3
#define BUF_R  4
__device__ __forceinline__ float* bufsel(int id) {
    switch (id) {
        case BUF_BM: return g_Bm;
        case BUF_T0: return g_T0;
        case BUF_T1: return g_T1;
        case BUF_RT: return g_Rt;
        default:     return g_R;
    }
}

// ---------------- packed f32x2 helpers (sm_103a FFMA2) ----------------
__device__ __forceinline__ unsigned long long dup2(float a) {
    unsigned long long r;
    asm("mov.b64 %0, {%1, %1};" : "=l"(r) : "f"(a));
    return r;
}
__device__ __forceinline__ unsigned long long fma2(unsigned long long a,
                                                   unsigned long long b,
                                                   unsigned long long c) {
    unsigned long long d;
    asm("fma.rn.f32x2 %0, %1, %2, %3;" : "=l"(d) : "l"(a), "l"(b), "l"(c));
    return d;
}
__device__ __forceinline__ float2 unpk(unsigned long long v) {
    float2 f;
    asm("mov.b64 {%0, %1}, %2;" : "=f"(f.x), "=f"(f.y) : "l"(v));
    return f;
}

// ---------------- 1) mean over S: deterministic two-stage ----------------
__global__ void mean_partial_kernel(const float* __restrict__ x) {
    int b = blockIdx.y, chunk = blockIdx.x;
    int t = threadIdx.x;
    int d = t & 127, half = t >> 7;
    const float* xp = x + ((size_t)b * S_ + (size_t)chunk * 1024 + half) * D_ + d;
    float s = 0.f;
    #pragma unroll 8
    for (int i = 0; i < 512; i++) { s += *xp; xp += 2 * D_; }
    __shared__ float red[256];
    red[t] = s;
    __syncthreads();
    if (t < 128) g_partial[(b * 8 + chunk) * D_ + d] = red[t] + red[t + 128];
}

// ---------------- 2) h = gelu(pooled @ W1^T + b1) ----------------
__global__ void h_kernel(const float* __restrict__ W1, const float* __restrict__ b1) {
    int b = blockIdx.x, t = threadIdx.x;
    __shared__ float ps[D_];
    if (t < D_) {
        float s = 0.f;
        #pragma unroll
        for (int c = 0; c < 8; c++) s += g_partial[(b * 8 + c) * D_ + t];
        ps[t] = s * (1.0f / (float)S_);
    }
    __syncthreads();
    float acc = b1[t];
    const float* w = W1 + (size_t)t * D_;
    #pragma unroll 8
    for (int k = 0; k < D_; k++) acc = fmaf(ps[k], w[k], acc);
    float z = acc;
    g_h[b * H_ + t] = 0.5f * z * (1.0f + erff(z * 0.70710678118654752f));
}

// ---------------- 3) P = W2 @ h^T + b2  -> P[r][b] ----------------
__global__ __launch_bounds__(128) void pgemm_kernel(const float* __restrict__ W2,
                                                    const float* __restrict__ b2) {
    extern __shared__ float sm[];
    float* hs = sm;                 // [512][16]  h transposed
    float* ws = sm + H_ * B_;       // [128][65]  W2 tile, padded
    int t = threadIdx.x;
    int row0 = blockIdx.x * 128;

    for (int idx = t; idx < H_ * B_; idx += 128) {
        int bb = idx >> 9, k = idx & 511;
        hs[k * B_ + bb] = g_h[idx];
    }

    unsigned long long acc[8];
    #pragma unroll
    for (int j = 0; j < 8; j++) acc[j] = 0ull;

    for (int kc = 0; kc < 8; kc++) {
        __syncthreads();
        for (int idx = t; idx < 128 * 64; idx += 128) {
            int r = idx >> 6, k = idx & 63;
            ws[r * 65 + k] = W2[(size_t)(row0 + r) * H_ + kc * 64 + k];
        }
        __syncthreads();
        #pragma unroll 4
        for (int k = 0; k < 64; k++) {
            unsigned long long wd = dup2(ws[t * 65 + k]);
            const float* hrow = &hs[(kc * 64 + k) * B_];
            ulonglong2 a = *(const ulonglong2*)(hrow);
            ulonglong2 bq = *(const ulonglong2*)(hrow + 4);
            ulonglong2 c = *(const ulonglong2*)(hrow + 8);
            ulonglong2 dq = *(const ulonglong2*)(hrow + 12);
            acc[0] = fma2(wd, a.x, acc[0]);  acc[1] = fma2(wd, a.y, acc[1]);
            acc[2] = fma2(wd, bq.x, acc[2]); acc[3] = fma2(wd, bq.y, acc[3]);
            acc[4] = fma2(wd, c.x, acc[4]);  acc[5] = fma2(wd, c.y, acc[5]);
            acc[6] = fma2(wd, dq.x, acc[6]); acc[7] = fma2(wd, dq.y, acc[7]);
        }
    }
    int r = row0 + t;
    float bias = b2[r];
    #pragma unroll
    for (int j = 0; j < 8; j++) {
        float2 f = unpk(acc[j]);
        float2 o = make_float2(f.x + bias, f.y + bias);
        *(float2*)&g_P[(size_t)r * B_ + 2 * j] = o;
    }
}

// ---------------- 4) B = 0.5*(P - P^T) * (1/8)  per (b,i) ----------------
__global__ void antisym_kernel() {
    int idx = blockIdx.x * 256 + threadIdx.x;      // 48*16384 total
    int m = idx >> 14;
    int rem = idx & 16383;
    int d = rem >> 7, e = rem & 127;
    int b = m / NROT, i = m - b * NROT;
    float pde = g_P[(size_t)(i * MATSZ + d * D_ + e) * B_ + b];
    float ped = g_P[(size_t)(i * MATSZ + e * D_ + d) * B_ + b];
    g_Bm[idx] = (pde - ped) * 0.0625f;             // 0.5 antisym * 1/8 scaling
}

// ---------------- 5) Taylor init: T0 = I + B/6 ----------------
__global__ void tinit_kernel() {
    int idx = blockIdx.x * 256 + threadIdx.x;
    int rem = idx & 16383;
    int d = rem >> 7, e = rem & 127;
    g_T0[idx] = g_Bm[idx] * (1.0f / 6.0f) + ((d == e) ? 1.0f : 0.0f);
}

// ---------------- 6) batched 128x128 matmul: C = alpha*(A@Bm) [+ I] ----------------
// Buffers addressed by ID (device-global resolution — see bufsel).
__global__ __launch_bounds__(256) void matmul_kernel(
    int idA, int offA, int strideA,
    int idB, int offB, int strideB,
    int idC, int strideC,
    float alpha, int addI) {
    extern __shared__ float sm[];
    float* As = sm;               // [128][128]
    float* Bs = sm + MATSZ;       // [128][64]
    int m = blockIdx.y, cs = blockIdx.x;
    const float* Ap = bufsel(idA) + offA + (size_t)m * strideA;
    const float* Bp = bufsel(idB) + offB + (size_t)m * strideB + cs * 64;
    int t = threadIdx.x;

    for (int idx = t; idx < MATSZ; idx += 256) As[idx] = Ap[idx];
    for (int idx = t; idx < 128 * 64; idx += 256) {
        int k = idx >> 6, c = idx & 63;
        Bs[idx] = Bp[k * D_ + c];
    }
    __syncthreads();

    int cg = t & 15, rg = t >> 4;
    int lc = cg * 4;
    unsigned long long acc[8][2];
    #pragma unroll
    for (int i = 0; i < 8; i++) { acc[i][0] = 0ull; acc[i][1] = 0ull; }

    #pragma unroll 2
    for (int k = 0; k < 128; k++) {
        ulonglong2 bv = *(const ulonglong2*)&Bs[k * 64 + lc];
        const float* arow = &As[(rg * 8) * D_ + k];
        #pragma unroll
        for (int i = 0; i < 8; i++) {
            unsigned long long ad = dup2(arow[i * D_]);
            acc[i][0] = fma2(ad, bv.x, acc[i][0]);
            acc[i][1] = fma2(ad, bv.y, acc[i][1]);
        }
    }

    float* Cp = bufsel(idC) + (size_t)m * strideC;
    int cbase = cs * 64 + lc;
    #pragma unroll
    for (int i = 0; i < 8; i++) {
        int r = rg * 8 + i;
        float2 f0 = unpk(acc[i][0]);
        float2 f1 = unpk(acc[i][1]);
        float v0 = alpha * f0.x, v1 = alpha * f0.y;
        float v2 = alpha * f1.x, v3 = alpha * f1.y;
        if (addI) {
            if (r == cbase + 0) v0 += 1.0f;
            if (r == cbase + 1) v1 += 1.0f;
            if (r == cbase + 2) v2 += 1.0f;
            if (r == cbase + 3) v3 += 1.0f;
        }
        *(float4*)&Cp[(size_t)r * D_ + cbase] = make_float4(v0, v1, v2, v3);
    }
}

// ---------------- 7) apply: y[b,s,:] = x[b,s,:] @ R_b ----------------
__global__ __launch_bounds__(256, 1) void apply_kernel(const float* __restrict__ x,
                                                       float* __restrict__ y) {
    extern __shared__ float sm[];
    float* Xs = sm;               // [128 rows][128 k]
    float* Rs = sm + MATSZ;       // [128 k][128 cols]
    int st = blockIdx.x, b = blockIdx.y;
    const float* xp = x + ((size_t)b * S_ + (size_t)st * 128) * D_;
    const float* Rp = g_R + (size_t)b * MATSZ;
    int t = threadIdx.x;

    for (int idx = t; idx < MATSZ; idx += 256) { Xs[idx] = xp[idx]; Rs[idx] = Rp[idx]; }
    __syncthreads();

    int cg = t & 15, rg = t >> 4;
    int c0 = cg * 8;
    unsigned long long acc[8][4];
    #pragma unroll
    for (int i = 0; i < 8; i++)
        #pragma unroll
        for (int j = 0; j < 4; j++) acc[i][j] = 0ull;

    #pragma unroll 2
    for (int k = 0; k < 128; k++) {
        ulonglong2 bv0 = *(const ulonglong2*)&Rs[k * D_ + c0];
        ulonglong2 bv1 = *(const ulonglong2*)&Rs[k * D_ + c0 + 4];
        const float* xr = &Xs[(rg * 8) * D_ + k];
        #pragma unroll
        for (int i = 0; i < 8; i++) {
            unsigned long long ad = dup2(xr[i * D_]);
            acc[i][0] = fma2(ad, bv0.x, acc[i][0]);
            acc[i][1] = fma2(ad, bv0.y, acc[i][1]);
            acc[i][2] = fma2(ad, bv1.x, acc[i][2]);
            acc[i][3] = fma2(ad, bv1.y, acc[i][3]);
        }
    }

    float* yp = y + ((size_t)b * S_ + (size_t)st * 128) * D_;
    #pragma unroll
    for (int i = 0; i < 8; i++) {
        int r = rg * 8 + i;
        float2 f0 = unpk(acc[i][0]);
        float2 f1 = unpk(acc[i][1]);
        float2 f2 = unpk(acc[i][2]);
        float2 f3 = unpk(acc[i][3]);
        *(float4*)&yp[(size_t)r * D_ + c0]     = make_float4(f0.x, f0.y, f1.x, f1.y);
        *(float4*)&yp[(size_t)r * D_ + c0 + 4] = make_float4(f2.x, f2.y, f3.x, f3.y);
    }
}

// ---------------- launch ----------------
extern "C" void kernel_launch(void* const* d_in, const int* in_sizes, int n_in,
                              void* d_out, int out_size) {
    const float* x  = (const float*)d_in[0];
    const float* W1 = (const float*)d_in[1];
    const float* b1 = (const float*)d_in[2];
    const float* W2 = (const float*)d_in[3];
    const float* b2 = (const float*)d_in[4];
    float* y = (float*)d_out;

    const int smem_pgemm  = (H_ * B_ + 128 * 65) * sizeof(float);   // 66048
    const int smem_matmul = (MATSZ + 128 * 64) * sizeof(float);     // 98304
    const int smem_apply  = (MATSZ * 2) * sizeof(float);            // 131072
    cudaFuncSetAttribute(pgemm_kernel,  cudaFuncAttributeMaxDynamicSharedMemorySize, smem_pgemm);
    cudaFuncSetAttribute(matmul_kernel, cudaFuncAttributeMaxDynamicSharedMemorySize, smem_matmul);
    cudaFuncSetAttribute(apply_kernel,  cudaFuncAttributeMaxDynamicSharedMemorySize, smem_apply);

    // 1) mean
    mean_partial_kernel<<<dim3(8, B_), 256>>>(x);
    // 2) hidden
    h_kernel<<<B_, H_>>>(W1, b1);
    // 3) params GEMM
    pgemm_kernel<<<W2ROWS / 128, 128, smem_pgemm>>>(W2, b2);
    // 4) antisymmetrize + pre-scale by 1/8
    antisym_kernel<<<(NMAT * MATSZ) / 256, 256>>>();
    // 5) Taylor order-6 with scaling s=3:  exp(g) = (exp(g/8))^8
    tinit_kernel<<<(NMAT * MATSZ) / 256, 256>>>();
    // Horner: T = I + c*(B @ T)
    matmul_kernel<<<dim3(2, NMAT), 256, smem_matmul>>>(BUF_BM, 0, MATSZ, BUF_T0, 0, MATSZ, BUF_T1, MATSZ, 1.0f/5.0f, 1);
    matmul_kernel<<<dim3(2, NMAT), 256, smem_matmul>>>(BUF_BM, 0, MATSZ, BUF_T1, 0, MATSZ, BUF_T0, MATSZ, 1.0f/4.0f, 1);
    matmul_kernel<<<dim3(2, NMAT), 256, smem_matmul>>>(BUF_BM, 0, MATSZ, BUF_T0, 0, MATSZ, BUF_T1, MATSZ, 1.0f/3.0f, 1);
    matmul_kernel<<<dim3(2, NMAT), 256, smem_matmul>>>(BUF_BM, 0, MATSZ, BUF_T1, 0, MATSZ, BUF_T0, MATSZ, 1.0f/2.0f, 1);
    matmul_kernel<<<dim3(2, NMAT), 256, smem_matmul>>>(BUF_BM, 0, MATSZ, BUF_T0, 0, MATSZ, BUF_T1, MATSZ, 1.0f,      1);
    // squarings: T1 -> T0 -> T1 -> T0 ; final exp in g_T0
    matmul_kernel<<<dim3(2, NMAT), 256, smem_matmul>>>(BUF_T1, 0, MATSZ, BUF_T1, 0, MATSZ, BUF_T0, MATSZ, 1.0f, 0);
    matmul_kernel<<<dim3(2, NMAT), 256, smem_matmul>>>(BUF_T0, 0, MATSZ, BUF_T0, 0, MATSZ, BUF_T1, MATSZ, 1.0f, 0);
    matmul_kernel<<<dim3(2, NMAT), 256, smem_matmul>>>(BUF_T1, 0, MATSZ, BUF_T1, 0, MATSZ, BUF_T0, MATSZ, 1.0f, 0);
    // 6) combine rotations per batch: R = rot0 @ rot1 @ rot2
    matmul_kernel<<<dim3(2, B_), 256, smem_matmul>>>(BUF_T0, 0, NROT * MATSZ,
                                                     BUF_T0, MATSZ, NROT * MATSZ,
                                                     BUF_RT, MATSZ, 1.0f, 0);
    matmul_kernel<<<dim3(2, B_), 256, smem_matmul>>>(BUF_RT, 0, MATSZ,
                                                     BUF_T0, 2 * MATSZ, NROT * MATSZ,
                                                     BUF_R, MATSZ, 1.0f, 0);
    // 7) apply fused rotation
    apply_kernel<<<dim3(S_ / 128, B_), 256, smem_apply>>>(x, y);
}

// round 4
// speedup vs baseline: 1.2358x; 1.2358x over previous
#include <cuda_runtime.h>
#include <cuda_bf16.h>
#include <math.h>
#include <stdint.h>

#define B_    16
#define S_    8192
#define D_    128
#define H_    512
#define NROT  3
#define NMAT  (B_ * NROT)          // 48
#define MATSZ (D_ * D_)            // 16384
#define W2ROWS (NROT * D_ * D_)    // 49152

// ---------------- scratch (static device globals; no allocs) ----------------
__device__ float g_partial[B_ * 8 * D_];
__device__ float g_h[B_ * H_];
__device__ float g_P[B_ * W2ROWS];          // P[b][r]
__device__ float g_Bm[NMAT * MATSZ];        // 0.5*(P - P^T)/8
__device__ float g_T0[NMAT * MATSZ];
__device__ float g_T1[NMAT * MATSZ];
__device__ float g_Rt[B_ * MATSZ];
__device__ float g_R [B_ * MATSZ];          // fused rotation R[k][n], fp32

#define BUF_BM 0
#define BUF_T0 1
#define BUF_T1 2
#define BUF_RT 3
#define BUF_R  4
__device__ __forceinline__ float* bufsel(int id) {
    switch (id) {
        case BUF_BM: return g_Bm;
        case BUF_T0: return g_T0;
        case BUF_T1: return g_T1;
        case BUF_RT: return g_Rt;
        default:     return g_R;
    }
}

// ---------------- packed f32x2 helpers (sm_103a FFMA2; base-target legal) ----------------
__device__ __forceinline__ unsigned long long dup2(float a) {
    unsigned long long r;
    asm("mov.b64 %0, {%1, %1};" : "=l"(r) : "f"(a));
    return r;
}
__device__ __forceinline__ unsigned long long fma2(unsigned long long a,
                                                   unsigned long long b,
                                                   unsigned long long c) {
    unsigned long long d;
    asm("fma.rn.f32x2 %0, %1, %2, %3;" : "=l"(d) : "l"(a), "l"(b), "l"(c));
    return d;
}
__device__ __forceinline__ float2 unpk(unsigned long long v) {
    float2 f;
    asm("mov.b64 {%0, %1}, %2;" : "=f"(f.x), "=f"(f.y) : "l"(v));
    return f;
}

// ---------------- mma.sync / ldmatrix helpers (sm_80+, assemble at compute_103) ----------
__device__ __forceinline__ uint32_t smem_u32(const void* p) {
    uint32_t a;
    asm("{ .reg .u64 t; cvta.to.shared.u64 t, %1; cvt.u32.u64 %0, t; }" : "=r"(a) : "l"(p));
    return a;
}
__device__ __forceinline__ void ldsm_x4(uint32_t* r, uint32_t addr) {
    asm volatile("ldmatrix.sync.aligned.m8n8.x4.shared.b16 {%0,%1,%2,%3}, [%4];"
                 : "=r"(r[0]), "=r"(r[1]), "=r"(r[2]), "=r"(r[3]) : "r"(addr));
}
__device__ __forceinline__ void ldsm_x2_trans(uint32_t* r, uint32_t addr) {
    asm volatile("ldmatrix.sync.aligned.m8n8.x2.trans.shared.b16 {%0,%1}, [%2];"
                 : "=r"(r[0]), "=r"(r[1]) : "r"(addr));
}
__device__ __forceinline__ void mma16816(float* c, const uint32_t* a, const uint32_t* b) {
    asm volatile("mma.sync.aligned.m16n8k16.row.col.f32.bf16.bf16.f32 "
                 "{%0,%1,%2,%3}, {%4,%5,%6,%7}, {%8,%9}, {%0,%1,%2,%3};"
                 : "+f"(c[0]), "+f"(c[1]), "+f"(c[2]), "+f"(c[3])
                 : "r"(a[0]), "r"(a[1]), "r"(a[2]), "r"(a[3]), "r"(b[0]), "r"(b[1]));
}

__device__ __forceinline__ void split_bf(float v, uint16_t& hi, uint16_t& lo) {
    __nv_bfloat16 h = __float2bfloat16(v);
    float hf = __bfloat162float(h);
    __nv_bfloat16 l = __float2bfloat16(v - hf);
    hi = *reinterpret_cast<uint16_t*>(&h);
    lo = *reinterpret_cast<uint16_t*>(&l);
}
__device__ __forceinline__ void split4(float4 v, uint32_t* hi, uint32_t* lo) {
    uint16_t h0, l0, h1, l1, h2, l2, h3, l3;
    split_bf(v.x, h0, l0); split_bf(v.y, h1, l1);
    split_bf(v.z, h2, l2); split_bf(v.w, h3, l3);
    hi[0] = (uint32_t)h0 | ((uint32_t)h1 << 16);
    hi[1] = (uint32_t)h2 | ((uint32_t)h3 << 16);
    lo[0] = (uint32_t)l0 | ((uint32_t)l1 << 16);
    lo[1] = (uint32_t)l2 | ((uint32_t)l3 << 16);
}

// smem plane layout (bf16 [128][136], conflict-free for ldmatrix)
#define LDA    136
#define PL_AH  0
#define PL_AL  34816
#define PL_BH  69632
#define PL_BL  104448
#define SMEM_BMM 139264   // also holds fp32 stage [128][132] = 67584B (reuses A planes)

// ---------------- unified 128x128x128 split-bf16 HMMA multiplier ----------------
// C = alpha * (A @ B) [+ I]; A, B, C fp32 row-major 128x128.
__device__ __forceinline__ void bmm_core(const float* __restrict__ A,
                                         const float* __restrict__ Bf,
                                         float* __restrict__ C,
                                         float alpha, int addI) {
    extern __shared__ char smc[];
    uint32_t sb = smem_u32(smc);
    int t = threadIdx.x;

    // load fp32, split to bf16 hi/lo planes
    for (int idx = t; idx < 4096; idx += 256) {
        int row = idx >> 5, c0 = (idx & 31) << 2;
        int eo = (row * LDA + c0) * 2;
        float4 va = *(const float4*)(A + (row << 7) + c0);
        uint32_t hi[2], lo[2];
        split4(va, hi, lo);
        *(uint32_t*)(smc + PL_AH + eo) = hi[0]; *(uint32_t*)(smc + PL_AH + eo + 4) = hi[1];
        *(uint32_t*)(smc + PL_AL + eo) = lo[0]; *(uint32_t*)(smc + PL_AL + eo + 4) = lo[1];
        float4 vb = *(const float4*)(Bf + (row << 7) + c0);
        split4(vb, hi, lo);
        *(uint32_t*)(smc + PL_BH + eo) = hi[0]; *(uint32_t*)(smc + PL_BH + eo + 4) = hi[1];
        *(uint32_t*)(smc + PL_BL + eo) = lo[0]; *(uint32_t*)(smc + PL_BL + eo + 4) = lo[1];
    }
    __syncthreads();

    int lane = t & 31, wid = t >> 5;
    int m0 = (wid & 3) << 5;      // 4 warp-rows of 32
    int n0 = (wid >> 2) << 6;     // 2 warp-cols of 64

    float acc[2][8][4];
    #pragma unroll
    for (int mi = 0; mi < 2; mi++)
        #pragma unroll
        for (int j = 0; j < 8; j++)
            #pragma unroll
            for (int q = 0; q < 4; q++) acc[mi][j][q] = 0.f;

    int arow = lane & 15;
    int acol = (lane >> 4) << 3;

    #pragma unroll
    for (int term = 0; term < 3; term++) {
        uint32_t pa = sb + (term == 1 ? PL_AL : PL_AH);
        uint32_t pb = sb + (term == 2 ? PL_BL : PL_BH);
        #pragma unroll
        for (int ks = 0; ks < 8; ks++) {
            int k0 = ks << 4;
            uint32_t a0[4], a1[4];
            ldsm_x4(a0, pa + (uint32_t)(((m0 + arow) * LDA + k0 + acol) << 1));
            ldsm_x4(a1, pa + (uint32_t)(((m0 + 16 + arow) * LDA + k0 + acol) << 1));
            uint32_t bfr[8][2];
            #pragma unroll
            for (int j = 0; j < 8; j++)
                ldsm_x2_trans(bfr[j], pb + (uint32_t)(((k0 + arow) * LDA + n0 + (j << 3)) << 1));
            #pragma unroll
            for (int j = 0; j < 8; j++) {
                mma16816(acc[0][j], a0, bfr[j]);
                mma16816(acc[1][j], a1, bfr[j]);
            }
        }
    }
    __syncthreads();   // all ldsm done; safe to reuse smem as fp32 stage

    float* stg = (float*)smc;  // [128][132]
    #pragma unroll
    for (int mi = 0; mi < 2; mi++)
        #pragma unroll
        for (int j = 0; j < 8; j++) {
            int r = m0 + (mi << 4) + (lane >> 2);
            int c = n0 + (j << 3) + ((lane & 3) << 1);
            float v0 = alpha * acc[mi][j][0], v1 = alpha * acc[mi][j][1];
            float v2 = alpha * acc[mi][j][2], v3 = alpha * acc[mi][j][3];
            if (addI) {
                if (r == c)         v0 += 1.0f;
                if (r == c + 1)     v1 += 1.0f;
                if (r + 8 == c)     v2 += 1.0f;
                if (r + 8 == c + 1) v3 += 1.0f;
            }
            *(float2*)(stg + r * 132 + c)       = make_float2(v0, v1);
            *(float2*)(stg + (r + 8) * 132 + c) = make_float2(v2, v3);
        }
    __syncthreads();
    for (int idx = t; idx < 4096; idx += 256) {
        int row = idx >> 5, c0 = (idx & 31) << 2;
        *(float4*)(C + (row << 7) + c0) = *(const float4*)(stg + row * 132 + c0);
    }
}

// chain wrapper: buffers by ID (device-resolved)
__global__ __launch_bounds__(256, 1) void bmm_chain_kernel(
    int idA, int offA, int strideA,
    int idB, int offB, int strideB,
    int idC, int strideC,
    float alpha, int addI) {
    int m = blockIdx.x;
    const float* A = bufsel(idA) + offA + (size_t)m * strideA;
    const float* Bf = bufsel(idB) + offB + (size_t)m * strideB;
    float* C = bufsel(idC) + (size_t)m * strideC;
    bmm_core(A, Bf, C, alpha, addI);
}

// apply wrapper: y[b, st*128:+128, :] = x_tile @ R_b
__global__ __launch_bounds__(256, 1) void apply_tc_kernel(const float* __restrict__ x,
                                                          float* __restrict__ y) {
    int st = blockIdx.x, b = blockIdx.y;
    const float* A = x + ((size_t)b * S_ + (size_t)st * 128) * D_;
    const float* Bf = g_R + (size_t)b * MATSZ;
    float* C = y + ((size_t)b * S_ + (size_t)st * 128) * D_;
    bmm_core(A, Bf, C, 1.0f, 0);
}

// ---------------- 1) mean over S ----------------
__global__ void mean_partial_kernel(const float* __restrict__ x) {
    int b = blockIdx.y, chunk = blockIdx.x;
    int t = threadIdx.x;
    int d = t & 127, half = t >> 7;
    const float* xp = x + ((size_t)b * S_ + (size_t)chunk * 1024 + half) * D_ + d;
    float s = 0.f;
    #pragma unroll 8
    for (int i = 0; i < 512; i++) { s += *xp; xp += 2 * D_; }
    __shared__ float red[256];
    red[t] = s;
    __syncthreads();
    if (t < 128) g_partial[(b * 8 + chunk) * D_ + d] = red[t] + red[t + 128];
}

// ---------------- 2) h = gelu(pooled @ W1^T + b1) ----------------
__global__ void h_kernel(const float* __restrict__ W1, const float* __restrict__ b1) {
    int b = blockIdx.x, t = threadIdx.x;
    __shared__ float ps[D_];
    if (t < D_) {
        float s = 0.f;
        #pragma unroll
        for (int c = 0; c < 8; c++) s += g_partial[(b * 8 + c) * D_ + t];
        ps[t] = s * (1.0f / (float)S_);
    }
    __syncthreads();
    float acc = b1[t];
    const float* w = W1 + (size_t)t * D_;
    #pragma unroll 8
    for (int k = 0; k < D_; k++) acc = fmaf(ps[k], w[k], acc);
    float z = acc;
    g_h[b * H_ + t] = 0.5f * z * (1.0f + erff(z * 0.70710678118654752f));
}

// ---------------- 3) P = W2 @ h^T + b2  -> P[b][r] ----------------
__global__ __launch_bounds__(128) void pgemm_kernel(const float* __restrict__ W2,
                                                    const float* __restrict__ b2) {
    extern __shared__ float sm[];
    float* hs = sm;                 // [512][16]
    float* ws = sm + H_ * B_;       // [128][65]
    int t = threadIdx.x;
    int row0 = blockIdx.x * 128;

    for (int idx = t; idx < H_ * B_; idx += 128) {
        int bb = idx >> 9, k = idx & 511;
        hs[k * B_ + bb] = g_h[idx];
    }

    unsigned long long acc[8];
    #pragma unroll
    for (int j = 0; j < 8; j++) acc[j] = 0ull;

    for (int kc = 0; kc < 8; kc++) {
        __syncthreads();
        for (int idx = t; idx < 128 * 64; idx += 128) {
            int r = idx >> 6, k = idx & 63;
            ws[r * 65 + k] = W2[(size_t)(row0 + r) * H_ + kc * 64 + k];
        }
        __syncthreads();
        #pragma unroll 4
        for (int k = 0; k < 64; k++) {
            unsigned long long wd = dup2(ws[t * 65 + k]);
            const float* hrow = &hs[(kc * 64 + k) * B_];
            ulonglong2 a = *(const ulonglong2*)(hrow);
            ulonglong2 bq = *(const ulonglong2*)(hrow + 4);
            ulonglong2 c = *(const ulonglong2*)(hrow + 8);
            ulonglong2 dq = *(const ulonglong2*)(hrow + 12);
            acc[0] = fma2(wd, a.x, acc[0]);  acc[1] = fma2(wd, a.y, acc[1]);
            acc[2] = fma2(wd, bq.x, acc[2]); acc[3] = fma2(wd, bq.y, acc[3]);
            acc[4] = fma2(wd, c.x, acc[4]);  acc[5] = fma2(wd, c.y, acc[5]);
            acc[6] = fma2(wd, dq.x, acc[6]); acc[7] = fma2(wd, dq.y, acc[7]);
        }
    }
    int r = row0 + t;
    float bias = b2[r];
    #pragma unroll
    for (int j = 0; j < 8; j++) {
        float2 f = unpk(acc[j]);
        g_P[(size_t)(2 * j)     * W2ROWS + r] = f.x + bias;
        g_P[(size_t)(2 * j + 1) * W2ROWS + r] = f.y + bias;
    }
}

// ---------------- 4) antisym + Taylor init fused ----------------
__global__ void antisym_tinit_kernel() {
    int idx = blockIdx.x * 256 + threadIdx.x;
    int m = idx >> 14;
    int rem = idx & 16383;
    int d = rem >> 7, e = rem & 127;
    int b = m / NROT, i = m - b * NROT;
    float pde = g_P[(size_t)b * W2ROWS + i * MATSZ + d * D_ + e];
    float ped = g_P[(size_t)b * W2ROWS + i * MATSZ + e * D_ + d];
    float v = (pde - ped) * 0.0625f;       // antisym*0.5 and /8 scaling
    g_Bm[idx] = v;
    g_T0[idx] = v * (1.0f / 6.0f) + ((d == e) ? 1.0f : 0.0f);
}

// ---------------- launch ----------------
extern "C" void kernel_launch(void* const* d_in, const int* in_sizes, int n_in,
                              void* d_out, int out_size) {
    const float* x  = (const float*)d_in[0];
    const float* W1 = (const float*)d_in[1];
    const float* b1 = (const float*)d_in[2];
    const float* W2 = (const float*)d_in[3];
    const float* b2 = (const float*)d_in[4];
    float* y = (float*)d_out;

    const int smem_pgemm = (H_ * B_ + 128 * 65) * sizeof(float);
    cudaFuncSetAttribute(pgemm_kernel, cudaFuncAttributeMaxDynamicSharedMemorySize, smem_pgemm);
    cudaFuncSetAttribute(bmm_chain_kernel, cudaFuncAttributeMaxDynamicSharedMemorySize, SMEM_BMM);
    cudaFuncSetAttribute(apply_tc_kernel,  cudaFuncAttributeMaxDynamicSharedMemorySize, SMEM_BMM);

    mean_partial_kernel<<<dim3(8, B_), 256>>>(x);
    h_kernel<<<B_, H_>>>(W1, b1);
    pgemm_kernel<<<W2ROWS / 128, 128, smem_pgemm>>>(W2, b2);
    antisym_tinit_kernel<<<(NMAT * MATSZ) / 256, 256>>>();

    // Taylor order-6, scaling s=3: Horner T = I + c*(Bm @ T)
    bmm_chain_kernel<<<NMAT, 256, SMEM_BMM>>>(BUF_BM, 0, MATSZ, BUF_T0, 0, MATSZ, BUF_T1, MATSZ, 1.0f/5.0f, 1);
    bmm_chain_kernel<<<NMAT, 256, SMEM_BMM>>>(BUF_BM, 0, MATSZ, BUF_T1, 0, MATSZ, BUF_T0, MATSZ, 1.0f/4.0f, 1);
    bmm_chain_kernel<<<NMAT, 256, SMEM_BMM>>>(BUF_BM, 0, MATSZ, BUF_T0, 0, MATSZ, BUF_T1, MATSZ, 1.0f/3.0f, 1);
    bmm_chain_kernel<<<NMAT, 256, SMEM_BMM>>>(BUF_BM, 0, MATSZ, BUF_T1, 0, MATSZ, BUF_T0, MATSZ, 1.0f/2.0f, 1);
    bmm_chain_kernel<<<NMAT, 256, SMEM_BMM>>>(BUF_BM, 0, MATSZ, BUF_T0, 0, MATSZ, BUF_T1, MATSZ, 1.0f,      1);
    // squarings: T1 -> T0 -> T1 -> T0
    bmm_chain_kernel<<<NMAT, 256, SMEM_BMM>>>(BUF_T1, 0, MATSZ, BUF_T1, 0, MATSZ, BUF_T0, MATSZ, 1.0f, 0);
    bmm_chain_kernel<<<NMAT, 256, SMEM_BMM>>>(BUF_T0, 0, MATSZ, BUF_T0, 0, MATSZ, BUF_T1, MATSZ, 1.0f, 0);
    bmm_chain_kernel<<<NMAT, 256, SMEM_BMM>>>(BUF_T1, 0, MATSZ, BUF_T1, 0, MATSZ, BUF_T0, MATSZ, 1.0f, 0);
    // combine: R = rot0 @ rot1 @ rot2
    bmm_chain_kernel<<<B_, 256, SMEM_BMM>>>(BUF_T0, 0, NROT * MATSZ,
                                            BUF_T0, MATSZ, NROT * MATSZ,
                                            BUF_RT, MATSZ, 1.0f, 0);
    bmm_chain_kernel<<<B_, 256, SMEM_BMM>>>(BUF_RT, 0, MATSZ,
                                            BUF_T0, 2 * MATSZ, NROT * MATSZ,
                                            BUF_R, MATSZ, 1.0f, 0);
    // apply fused rotation via tensor cores
    apply_tc_kernel<<<dim3(S_ / 128, B_), 256, SMEM_BMM>>>(x, y);
}

// round 5
// speedup vs baseline: 2.3174x; 1.8752x over previous
#include <cuda_runtime.h>
#include <cuda_bf16.h>
#include <math.h>
#include <stdint.h>

#define B_    16
#define S_    8192
#define D_    128
#define H_    512
#define NROT  3
#define NMAT  (B_ * NROT)          // 48
#define MATSZ (D_ * D_)            // 16384
#define W2ROWS (NROT * D_ * D_)    // 49152

// ---------------- scratch ----------------
__device__ float g_partial[B_ * 8 * D_];
__device__ float g_h[B_ * H_];
__device__ float g_P[B_ * W2ROWS];          // P[b][r]
__device__ float g_Bm[NMAT * MATSZ];        // A = 0.5*(P - P^T)/8
__device__ float g_Dl[NMAT * MATSZ];        // Delta = expm(g) - I per matrix
__device__ uint32_t g_frag[B_ * 8192];      // bf16 B-fragments of Delta_R per batch

// ---------------- packed f32x2 (pgemm) ----------------
__device__ __forceinline__ unsigned long long dup2(float a) {
    unsigned long long r; asm("mov.b64 %0, {%1, %1};" : "=l"(r) : "f"(a)); return r;
}
__device__ __forceinline__ unsigned long long fma2(unsigned long long a,
                                                   unsigned long long b,
                                                   unsigned long long c) {
    unsigned long long d;
    asm("fma.rn.f32x2 %0, %1, %2, %3;" : "=l"(d) : "l"(a), "l"(b), "l"(c));
    return d;
}
__device__ __forceinline__ float2 unpk(unsigned long long v) {
    float2 f; asm("mov.b64 {%0, %1}, %2;" : "=f"(f.x), "=f"(f.y) : "l"(v)); return f;
}

// ---------------- mma.sync / ldmatrix helpers ----------------
__device__ __forceinline__ uint32_t smem_u32(const void* p) {
    uint32_t a;
    asm("{ .reg .u64 t; cvta.to.shared.u64 t, %1; cvt.u32.u64 %0, t; }" : "=r"(a) : "l"(p));
    return a;
}
__device__ __forceinline__ void ldsm_x4(uint32_t* r, uint32_t addr) {
    asm volatile("ldmatrix.sync.aligned.m8n8.x4.shared.b16 {%0,%1,%2,%3}, [%4];"
                 : "=r"(r[0]), "=r"(r[1]), "=r"(r[2]), "=r"(r[3]) : "r"(addr));
}
__device__ __forceinline__ void ldsm_x2_trans(uint32_t* r, uint32_t addr) {
    asm volatile("ldmatrix.sync.aligned.m8n8.x2.trans.shared.b16 {%0,%1}, [%2];"
                 : "=r"(r[0]), "=r"(r[1]) : "r"(addr));
}
__device__ __forceinline__ void mma16816(float* c, const uint32_t* a, const uint32_t* b) {
    asm volatile("mma.sync.aligned.m16n8k16.row.col.f32.bf16.bf16.f32 "
                 "{%0,%1,%2,%3}, {%4,%5,%6,%7}, {%8,%9}, {%0,%1,%2,%3};"
                 : "+f"(c[0]), "+f"(c[1]), "+f"(c[2]), "+f"(c[3])
                 : "r"(a[0]), "r"(a[1]), "r"(a[2]), "r"(a[3]), "r"(b[0]), "r"(b[1]));
}
__device__ __forceinline__ uint32_t pack_bf2(float a, float b) {
    __nv_bfloat162 h = __floats2bfloat162_rn(a, b);
    return *reinterpret_cast<uint32_t*>(&h);
}
__device__ __forceinline__ float bflo(uint32_t w) { return __uint_as_float(w << 16); }
__device__ __forceinline__ float bfhi(uint32_t w) { return __uint_as_float(w & 0xffff0000u); }
__device__ __forceinline__ void split_bf(float v, uint16_t& hi, uint16_t& lo) {
    __nv_bfloat16 h = __float2bfloat16(v);
    float hf = __bfloat162float(h);
    __nv_bfloat16 l = __float2bfloat16(v - hf);
    hi = *reinterpret_cast<uint16_t*>(&h);
    lo = *reinterpret_cast<uint16_t*>(&l);
}

#define LDA 136                      // bf16 plane row stride (elements)
// chain/combine smem layout (bytes)
#define CH_AH 0
#define CH_DH 34816
#define CH_AF 69632                  // fp32 [128][128]
#define CH_ST 135168                 // fp32 [128][132]
#define CH_TOTAL 202752
// apply smem layout
#define AP_XH 0
#define AP_XL 34816
#define AP_TOTAL 69632

// 1-pass 128x128x128 bf16 MMA: acc += A(pa) @ B(pb), planes in smem
__device__ __forceinline__ void mma128(uint32_t pa, uint32_t pb,
                                       float acc[2][8][4], int lane, int wid) {
    int m0 = (wid & 3) << 5, n0 = (wid >> 2) << 6;
    int arow = lane & 15, acol = (lane >> 4) << 3;
    #pragma unroll
    for (int ks = 0; ks < 8; ks++) {
        int k0 = ks << 4;
        uint32_t a0[4], a1[4];
        ldsm_x4(a0, pa + (uint32_t)(((m0 + arow) * LDA + k0 + acol) << 1));
        ldsm_x4(a1, pa + (uint32_t)(((m0 + 16 + arow) * LDA + k0 + acol) << 1));
        uint32_t bfr[8][2];
        #pragma unroll
        for (int j = 0; j < 8; j++)
            ldsm_x2_trans(bfr[j], pb + (uint32_t)(((k0 + arow) * LDA + n0 + (j << 3)) << 1));
        #pragma unroll
        for (int j = 0; j < 8; j++) {
            mma16816(acc[0][j], a0, bfr[j]);
            mma16816(acc[1][j], a1, bfr[j]);
        }
    }
}

// ---------------- 1) mean over S (float4) ----------------
__global__ void mean_partial_kernel(const float* __restrict__ x) {
    int b = blockIdx.y, chunk = blockIdx.x;
    int t = threadIdx.x, lane = t & 31, grp = t >> 5;
    const float* xp = x + ((size_t)b * S_ + (size_t)chunk * 1024 + grp) * D_ + lane * 4;
    float4 s = make_float4(0.f, 0.f, 0.f, 0.f);
    #pragma unroll 4
    for (int i = 0; i < 128; i++) {
        float4 v = *(const float4*)xp;
        s.x += v.x; s.y += v.y; s.z += v.z; s.w += v.w;
        xp += 8 * D_;
    }
    __shared__ float4 red[256];
    red[t] = s;
    __syncthreads();
    if (grp < 4) {
        float4 o = red[t + 128];
        red[t] = make_float4(red[t].x + o.x, red[t].y + o.y, red[t].z + o.z, red[t].w + o.w);
    }
    __syncthreads();
    if (grp < 2) {
        float4 o = red[t + 64];
        red[t] = make_float4(red[t].x + o.x, red[t].y + o.y, red[t].z + o.z, red[t].w + o.w);
    }
    __syncthreads();
    if (grp == 0) {
        float4 o = red[t + 32];
        float4 r = make_float4(red[t].x + o.x, red[t].y + o.y, red[t].z + o.z, red[t].w + o.w);
        *(float4*)&g_partial[(b * 8 + chunk) * D_ + lane * 4] = r;
    }
}

// ---------------- 2) h = gelu(pooled @ W1^T + b1) ----------------
__global__ void h_kernel(const float* __restrict__ W1, const float* __restrict__ b1) {
    int b = blockIdx.x, t = threadIdx.x;
    __shared__ float ps[D_];
    if (t < D_) {
        float s = 0.f;
        #pragma unroll
        for (int c = 0; c < 8; c++) s += g_partial[(b * 8 + c) * D_ + t];
        ps[t] = s * (1.0f / (float)S_);
    }
    __syncthreads();
    float acc = b1[t];
    const float* w = W1 + (size_t)t * D_;
    #pragma unroll 8
    for (int k = 0; k < D_; k++) acc = fmaf(ps[k], w[k], acc);
    float z = acc;
    g_h[b * H_ + t] = 0.5f * z * (1.0f + erff(z * 0.70710678118654752f));
}

// ---------------- 3) P = W2 @ h^T + b2 -> P[b][r] (float4 loads) ----------------
#define WS_LD 68
__global__ __launch_bounds__(128) void pgemm_kernel(const float* __restrict__ W2,
                                                    const float* __restrict__ b2) {
    extern __shared__ float sm[];
    float* hs = sm;                   // [512][16]
    float* ws = sm + H_ * B_;         // [128][68]
    int t = threadIdx.x;
    int row0 = blockIdx.x * 128;

    for (int idx = t; idx < H_ * B_; idx += 128) {
        int bb = idx >> 9, k = idx & 511;
        hs[k * B_ + bb] = g_h[idx];
    }

    unsigned long long acc[8];
    #pragma unroll
    for (int j = 0; j < 8; j++) acc[j] = 0ull;

    for (int kc = 0; kc < 8; kc++) {
        __syncthreads();
        for (int idx = t; idx < 2048; idx += 128) {
            int r = idx >> 4, k4 = (idx & 15) << 2;
            *(float4*)&ws[r * WS_LD + k4] =
                *(const float4*)&W2[(size_t)(row0 + r) * H_ + kc * 64 + k4];
        }
        __syncthreads();
        #pragma unroll 4
        for (int k = 0; k < 64; k++) {
            unsigned long long wd = dup2(ws[t * WS_LD + k]);
            const float* hrow = &hs[(kc * 64 + k) * B_];
            ulonglong2 a = *(const ulonglong2*)(hrow);
            ulonglong2 bq = *(const ulonglong2*)(hrow + 4);
            ulonglong2 c = *(const ulonglong2*)(hrow + 8);
            ulonglong2 dq = *(const ulonglong2*)(hrow + 12);
            acc[0] = fma2(wd, a.x, acc[0]);  acc[1] = fma2(wd, a.y, acc[1]);
            acc[2] = fma2(wd, bq.x, acc[2]); acc[3] = fma2(wd, bq.y, acc[3]);
            acc[4] = fma2(wd, c.x, acc[4]);  acc[5] = fma2(wd, c.y, acc[5]);
            acc[6] = fma2(wd, dq.x, acc[6]); acc[7] = fma2(wd, dq.y, acc[7]);
        }
    }
    int r = row0 + t;
    float bias = b2[r];
    #pragma unroll
    for (int j = 0; j < 8; j++) {
        float2 f = unpk(acc[j]);
        g_P[(size_t)(2 * j)     * W2ROWS + r] = f.x + bias;
        g_P[(size_t)(2 * j + 1) * W2ROWS + r] = f.y + bias;
    }
}

// ---------------- 4) A = 0.5*(P - P^T)/8 ----------------
__global__ void antisym_kernel() {
    int idx = blockIdx.x * 256 + threadIdx.x;
    int m = idx >> 14;
    int rem = idx & 16383;
    int d = rem >> 7, e = rem & 127;
    int b = m / NROT, i = m - b * NROT;
    float pde = g_P[(size_t)b * W2ROWS + i * MATSZ + d * D_ + e];
    float ped = g_P[(size_t)b * W2ROWS + i * MATSZ + e * D_ + d];
    g_Bm[idx] = (pde - ped) * 0.0625f;     // 0.5 antisym * 1/8 scaling
}

// ---------------- 5) fused expm chain: Delta = expm(8A) - I, one launch ----------------
// Order-4 Taylor + 3 squarings, all matmuls 1-pass bf16 on small operands.
__global__ __launch_bounds__(256, 1) void expm_chain_kernel() {
    extern __shared__ char smc[];
    uint32_t sb = smem_u32(smc);
    float* AF = (float*)(smc + CH_AF);
    float* ST = (float*)(smc + CH_ST);
    int t = threadIdx.x, lane = t & 31, wid = t >> 5;
    int m = blockIdx.x;
    const float* G = g_Bm + (size_t)m * MATSZ;

    // load A (fp32 + bf16 plane), init stage = A/4
    for (int idx = t; idx < 4096; idx += 256) {
        int row = idx >> 5, c0 = (idx & 31) << 2;
        float4 v = *(const float4*)(G + (row << 7) + c0);
        *(float4*)(AF + (row << 7) + c0) = v;
        int eo = (row * LDA + c0) << 1;
        *(uint32_t*)(smc + CH_AH + eo)     = pack_bf2(v.x, v.y);
        *(uint32_t*)(smc + CH_AH + eo + 4) = pack_bf2(v.z, v.w);
        *(float4*)(ST + row * 132 + c0) =
            make_float4(v.x * 0.25f, v.y * 0.25f, v.z * 0.25f, v.w * 0.25f);
    }
    __syncthreads();

    int m0 = (wid & 3) << 5, n0 = (wid >> 2) << 6;

    // Horner: Delta <- (A + A@Delta)/c for c = 3, 2, 1
    #pragma unroll 1
    for (int step = 0; step < 3; step++) {
        float invc = (step == 0) ? (1.f / 3.f) : (step == 1 ? 0.5f : 1.f);
        for (int idx = t; idx < 4096; idx += 256) {
            int row = idx >> 5, c0 = (idx & 31) << 2;
            float4 v = *(const float4*)(ST + row * 132 + c0);
            int eo = (row * LDA + c0) << 1;
            *(uint32_t*)(smc + CH_DH + eo)     = pack_bf2(v.x, v.y);
            *(uint32_t*)(smc + CH_DH + eo + 4) = pack_bf2(v.z, v.w);
        }
        __syncthreads();
        float acc[2][8][4];
        #pragma unroll
        for (int mi = 0; mi < 2; mi++)
            #pragma unroll
            for (int j = 0; j < 8; j++)
                #pragma unroll
                for (int q = 0; q < 4; q++) acc[mi][j][q] = 0.f;
        mma128(sb + CH_AH, sb + CH_DH, acc, lane, wid);
        #pragma unroll
        for (int mi = 0; mi < 2; mi++)
            #pragma unroll
            for (int j = 0; j < 8; j++) {
                int r = m0 + (mi << 4) + (lane >> 2);
                int c = n0 + (j << 3) + ((lane & 3) << 1);
                ST[r * 132 + c]           = (AF[(r << 7) + c]       + acc[mi][j][0]) * invc;
                ST[r * 132 + c + 1]       = (AF[(r << 7) + c + 1]   + acc[mi][j][1]) * invc;
                ST[(r + 8) * 132 + c]     = (AF[((r + 8) << 7) + c]     + acc[mi][j][2]) * invc;
                ST[(r + 8) * 132 + c + 1] = (AF[((r + 8) << 7) + c + 1] + acc[mi][j][3]) * invc;
            }
        __syncthreads();
    }

    // Squarings: Delta <- 2*Delta + Delta^2, x3
    #pragma unroll 1
    for (int sq = 0; sq < 3; sq++) {
        for (int idx = t; idx < 4096; idx += 256) {
            int row = idx >> 5, c0 = (idx & 31) << 2;
            float4 v = *(const float4*)(ST + row * 132 + c0);
            int eo = (row * LDA + c0) << 1;
            *(uint32_t*)(smc + CH_DH + eo)     = pack_bf2(v.x, v.y);
            *(uint32_t*)(smc + CH_DH + eo + 4) = pack_bf2(v.z, v.w);
        }
        __syncthreads();
        float acc[2][8][4];
        #pragma unroll
        for (int mi = 0; mi < 2; mi++)
            #pragma unroll
            for (int j = 0; j < 8; j++)
                #pragma unroll
                for (int q = 0; q < 4; q++) acc[mi][j][q] = 0.f;
        mma128(sb + CH_DH, sb + CH_DH, acc, lane, wid);
        #pragma unroll
        for (int mi = 0; mi < 2; mi++)
            #pragma unroll
            for (int j = 0; j < 8; j++) {
                int r = m0 + (mi << 4) + (lane >> 2);
                int c = n0 + (j << 3) + ((lane & 3) << 1);
                ST[r * 132 + c]           = 2.f * ST[r * 132 + c]           + acc[mi][j][0];
                ST[r * 132 + c + 1]       = 2.f * ST[r * 132 + c + 1]       + acc[mi][j][1];
                ST[(r + 8) * 132 + c]     = 2.f * ST[(r + 8) * 132 + c]     + acc[mi][j][2];
                ST[(r + 8) * 132 + c + 1] = 2.f * ST[(r + 8) * 132 + c + 1] + acc[mi][j][3];
            }
        __syncthreads();
    }

    float* out = g_Dl + (size_t)m * MATSZ;
    for (int idx = t; idx < 4096; idx += 256) {
        int row = idx >> 5, c0 = (idx & 31) << 2;
        *(float4*)(out + (row << 7) + c0) = *(const float4*)(ST + row * 132 + c0);
    }
}

// ---------------- 6) combine: Delta_R = D0+D1+D0@D1, then +D2+(.)@D2; emit frags ----
__global__ __launch_bounds__(256, 1) void combine_kernel() {
    extern __shared__ char smc[];
    uint32_t sb = smem_u32(smc);
    float* AF = (float*)(smc + CH_AF);
    float* ST = (float*)(smc + CH_ST);
    int t = threadIdx.x, lane = t & 31, wid = t >> 5;
    int b = blockIdx.x;
    int m0 = (wid & 3) << 5, n0 = (wid >> 2) << 6;

    // phase 1: D0 -> AF + AH;  D1 -> ST + DH
    {
        const float* D0 = g_Dl + (size_t)(b * 3 + 0) * MATSZ;
        const float* D1 = g_Dl + (size_t)(b * 3 + 1) * MATSZ;
        for (int idx = t; idx < 4096; idx += 256) {
            int row = idx >> 5, c0 = (idx & 31) << 2;
            int eo = (row * LDA + c0) << 1;
            float4 v0 = *(const float4*)(D0 + (row << 7) + c0);
            *(float4*)(AF + (row << 7) + c0) = v0;
            *(uint32_t*)(smc + CH_AH + eo)     = pack_bf2(v0.x, v0.y);
            *(uint32_t*)(smc + CH_AH + eo + 4) = pack_bf2(v0.z, v0.w);
            float4 v1 = *(const float4*)(D1 + (row << 7) + c0);
            *(float4*)(ST + row * 132 + c0) = v1;
            *(uint32_t*)(smc + CH_DH + eo)     = pack_bf2(v1.x, v1.y);
            *(uint32_t*)(smc + CH_DH + eo + 4) = pack_bf2(v1.z, v1.w);
        }
        __syncthreads();
        float acc[2][8][4];
        #pragma unroll
        for (int mi = 0; mi < 2; mi++)
            #pragma unroll
            for (int j = 0; j < 8; j++)
                #pragma unroll
                for (int q = 0; q < 4; q++) acc[mi][j][q] = 0.f;
        mma128(sb + CH_AH, sb + CH_DH, acc, lane, wid);
        #pragma unroll
        for (int mi = 0; mi < 2; mi++)
            #pragma unroll
            for (int j = 0; j < 8; j++) {
                int r = m0 + (mi << 4) + (lane >> 2);
                int c = n0 + (j << 3) + ((lane & 3) << 1);
                ST[r * 132 + c]           += AF[(r << 7) + c]           + acc[mi][j][0];
                ST[r * 132 + c + 1]       += AF[(r << 7) + c + 1]       + acc[mi][j][1];
                ST[(r + 8) * 132 + c]     += AF[((r + 8) << 7) + c]     + acc[mi][j][2];
                ST[(r + 8) * 132 + c + 1] += AF[((r + 8) << 7) + c + 1] + acc[mi][j][3];
            }
        __syncthreads();
    }
    // phase 2: A = D01 (from ST) -> AH;  D2 -> AF + DH
    {
        const float* D2 = g_Dl + (size_t)(b * 3 + 2) * MATSZ;
        for (int idx = t; idx < 4096; idx += 256) {
            int row = idx >> 5, c0 = (idx & 31) << 2;
            int eo = (row * LDA + c0) << 1;
            float4 v = *(const float4*)(ST + row * 132 + c0);
            *(uint32_t*)(smc + CH_AH + eo)     = pack_bf2(v.x, v.y);
            *(uint32_t*)(smc + CH_AH + eo + 4) = pack_bf2(v.z, v.w);
            float4 v2 = *(const float4*)(D2 + (row << 7) + c0);
            *(float4*)(AF + (row << 7) + c0) = v2;
            *(uint32_t*)(smc + CH_DH + eo)     = pack_bf2(v2.x, v2.y);
            *(uint32_t*)(smc + CH_DH + eo + 4) = pack_bf2(v2.z, v2.w);
        }
        __syncthreads();
        float acc[2][8][4];
        #pragma unroll
        for (int mi = 0; mi < 2; mi++)
            #pragma unroll
            for (int j = 0; j < 8; j++)
                #pragma unroll
                for (int q = 0; q < 4; q++) acc[mi][j][q] = 0.f;
        mma128(sb + CH_AH, sb + CH_DH, acc, lane, wid);
        #pragma unroll
        for (int mi = 0; mi < 2; mi++)
            #pragma unroll
            for (int j = 0; j < 8; j++) {
                int r = m0 + (mi << 4) + (lane >> 2);
                int c = n0 + (j << 3) + ((lane & 3) << 1);
                ST[r * 132 + c]           += AF[(r << 7) + c]           + acc[mi][j][0];
                ST[r * 132 + c + 1]       += AF[(r << 7) + c + 1]       + acc[mi][j][1];
                ST[(r + 8) * 132 + c]     += AF[((r + 8) << 7) + c]     + acc[mi][j][2];
                ST[(r + 8) * 132 + c + 1] += AF[((r + 8) << 7) + c + 1] + acc[mi][j][3];
            }
        __syncthreads();
    }
    // emit bf16 B-fragments of Delta_R for mma m16n8k16 row.col
    // word index: ((ks*16 + jg)*32 + lane)*2 + reg
    for (int idx = t; idx < 8192; idx += 256) {
        int reg = idx & 1;
        int ln = (idx >> 1) & 31;
        int jg = (idx >> 6) & 15;
        int ks = idx >> 10;
        int k0 = ks * 16 + ((ln & 3) << 1) + reg * 8;
        int n = jg * 8 + (ln >> 2);
        g_frag[(size_t)b * 8192 + idx] = pack_bf2(ST[k0 * 132 + n], ST[(k0 + 1) * 132 + n]);
    }
}

// ---------------- 7) apply: y = x + x@Delta_R (2-pass split-bf16 HMMA) ----------------
__global__ __launch_bounds__(256) void apply_kernel(const float* __restrict__ x,
                                                    float* __restrict__ y) {
    extern __shared__ char smc[];
    uint32_t sb = smem_u32(smc);
    int t = threadIdx.x, lane = t & 31, wid = t >> 5;
    int st = blockIdx.x, b = blockIdx.y;
    const float* xp = x + ((size_t)b * S_ + (size_t)st * 128) * D_;

    for (int idx = t; idx < 8192; idx += 256) {
        int row = idx >> 6, j = idx & 63, col = j << 1;
        float2 v = *(const float2*)(xp + (row << 7) + col);
        uint16_t h0, l0, h1, l1;
        split_bf(v.x, h0, l0);
        split_bf(v.y, h1, l1);
        int eo = (row * LDA + col) << 1;
        *(uint32_t*)(smc + AP_XH + eo) = (uint32_t)h0 | ((uint32_t)h1 << 16);
        *(uint32_t*)(smc + AP_XL + eo) = (uint32_t)l0 | ((uint32_t)l1 << 16);
    }
    __syncthreads();

    int m0 = (wid & 3) << 5, n0 = (wid >> 2) << 6;
    int arow = lane & 15, acol = (lane >> 4) << 3;
    int jgbase = (wid >> 2) << 3;

    float acc[2][8][4];
    #pragma unroll
    for (int mi = 0; mi < 2; mi++)
        #pragma unroll
        for (int j = 0; j < 8; j++)
            #pragma unroll
            for (int q = 0; q < 4; q++) acc[mi][j][q] = 0.f;

    const uint2* fp = (const uint2*)(g_frag + (size_t)b * 8192);
    #pragma unroll
    for (int ks = 0; ks < 8; ks++) {
        int k0 = ks << 4;
        uint2 bfr[8];
        #pragma unroll
        for (int j = 0; j < 8; j++)
            bfr[j] = fp[(ks * 16 + jgbase + j) * 32 + lane];
        uint32_t a0[4], a1[4];
        ldsm_x4(a0, sb + AP_XH + (uint32_t)(((m0 + arow) * LDA + k0 + acol) << 1));
        ldsm_x4(a1, sb + AP_XH + (uint32_t)(((m0 + 16 + arow) * LDA + k0 + acol) << 1));
        #pragma unroll
        for (int j = 0; j < 8; j++) {
            mma16816(acc[0][j], a0, (const uint32_t*)&bfr[j]);
            mma16816(acc[1][j], a1, (const uint32_t*)&bfr[j]);
        }
        ldsm_x4(a0, sb + AP_XL + (uint32_t)(((m0 + arow) * LDA + k0 + acol) << 1));
        ldsm_x4(a1, sb + AP_XL + (uint32_t)(((m0 + 16 + arow) * LDA + k0 + acol) << 1));
        #pragma unroll
        for (int j = 0; j < 8; j++) {
            mma16816(acc[0][j], a0, (const uint32_t*)&bfr[j]);
            mma16816(acc[1][j], a1, (const uint32_t*)&bfr[j]);
        }
    }

    float* yp = y + ((size_t)b * S_ + (size_t)st * 128) * D_;
    #pragma unroll
    for (int mi = 0; mi < 2; mi++)
        #pragma unroll
        for (int j = 0; j < 8; j++) {
            int r = m0 + (mi << 4) + (lane >> 2);
            int c = n0 + (j << 3) + ((lane & 3) << 1);
            uint32_t wh = *(uint32_t*)(smc + AP_XH + ((r * LDA + c) << 1));
            uint32_t wl = *(uint32_t*)(smc + AP_XL + ((r * LDA + c) << 1));
            float x0 = bflo(wh) + bflo(wl), x1 = bfhi(wh) + bfhi(wl);
            *(float2*)(yp + (r << 7) + c) =
                make_float2(acc[mi][j][0] + x0, acc[mi][j][1] + x1);
            wh = *(uint32_t*)(smc + AP_XH + (((r + 8) * LDA + c) << 1));
            wl = *(uint32_t*)(smc + AP_XL + (((r + 8) * LDA + c) << 1));
            x0 = bflo(wh) + bflo(wl); x1 = bfhi(wh) + bfhi(wl);
            *(float2*)(yp + ((r + 8) << 7) + c) =
                make_float2(acc[mi][j][2] + x0, acc[mi][j][3] + x1);
        }
}

// ---------------- launch ----------------
extern "C" void kernel_launch(void* const* d_in, const int* in_sizes, int n_in,
                              void* d_out, int out_size) {
    const float* x  = (const float*)d_in[0];
    const float* W1 = (const float*)d_in[1];
    const float* b1 = (const float*)d_in[2];
    const float* W2 = (const float*)d_in[3];
    const float* b2 = (const float*)d_in[4];
    float* y = (float*)d_out;

    const int smem_pgemm = (H_ * B_ + 128 * WS_LD) * sizeof(float);   // 67584
    cudaFuncSetAttribute(pgemm_kernel, cudaFuncAttributeMaxDynamicSharedMemorySize, smem_pgemm);
    cudaFuncSetAttribute(expm_chain_kernel, cudaFuncAttributeMaxDynamicSharedMemorySize, CH_TOTAL);
    cudaFuncSetAttribute(combine_kernel, cudaFuncAttributeMaxDynamicSharedMemorySize, CH_TOTAL);
    cudaFuncSetAttribute(apply_kernel, cudaFuncAttributeMaxDynamicSharedMemorySize, AP_TOTAL);

    mean_partial_kernel<<<dim3(8, B_), 256>>>(x);
    h_kernel<<<B_, H_>>>(W1, b1);
    pgemm_kernel<<<W2ROWS / 128, 128, smem_pgemm>>>(W2, b2);
    antisym_kernel<<<(NMAT * MATSZ) / 256, 256>>>();
    expm_chain_kernel<<<NMAT, 256, CH_TOTAL>>>();
    combine_kernel<<<B_, 256, CH_TOTAL>>>();
    apply_kernel<<<dim3(S_ / 128, B_), 256, AP_TOTAL>>>(x, y);
}